// round 15
// baseline (speedup 1.0000x reference)
#include <cuda_runtime.h>
#include <cuda_fp16.h>
#include <cstdint>

// Shape fixed by dataset: B=4, T=2048, C=1024, fp32 in/out.
#define BATCH 4
#define SEQ   2048
#define CH    1024

#define TM 128
#define TN 256
#define BK 32          // K elems per chunk (fp16) = 64B rows
#define STAGES 5

#define STG_A_H 0
#define STG_A_L 8192
#define STG_B_H 16384
#define STG_BYTES 32768
#define SMEM_BYTES (STAGES * STG_BYTES)   // 160 KB

#define SWZ64(o) ((o) ^ ((((unsigned)(o)) >> 3) & 0x30u))

// ---------------- scratch (__device__ globals; no allocs allowed) -------------
__device__ __half g_xh[(size_t)BATCH*SEQ*CH], g_xl[(size_t)BATCH*SEQ*CH];
__device__ __half g_wqth[CH*CH], g_wqtl[CH*CH];   // Wq^T split
__device__ __half g_wkth[CH*CH], g_wktl[CH*CH];   // Wk^T split
__device__ __half g_wvh[CH*CH],  g_wvl[CH*CH];
__device__ __half g_gth[CH*CH];                   // Gt = 512*scale*(Wk^T Wq), hi only
__device__ __half g_yh[(size_t)BATCH*SEQ*CH], g_yl[(size_t)BATCH*SEQ*CH];   // Y*16 split
__device__ __half g_vth[(size_t)BATCH*CH*SEQ];    // V^T [b][c][t], hi only
__device__ float  g_S [(size_t)BATCH*SEQ*SEQ];
__device__ __half g_ph[(size_t)BATCH*SEQ*SEQ];    // P hi only

// ---------------- helpers ----------------
__device__ __forceinline__ uint32_t smem_u32(const void* p){
    uint32_t a;
    asm("{ .reg .u64 t; cvta.to.shared.u64 t, %1; cvt.u32.u64 %0, t; }" : "=r"(a) : "l"(p));
    return a;
}
__device__ __forceinline__ void split1(float v, __half& h, __half& l){
    h = __float2half_rn(v);
    l = __float2half_rn(v - __half2float(h));
}
__device__ __forceinline__ uint32_t pack2(__half a, __half b){
    __half2 p = __halves2half2(a, b);
    return *(uint32_t*)&p;
}
__device__ __forceinline__ void ldsm4(uint32_t* r, uint32_t a){
    asm volatile("ldmatrix.sync.aligned.m8n8.x4.shared.b16 {%0,%1,%2,%3}, [%4];"
        : "=r"(r[0]),"=r"(r[1]),"=r"(r[2]),"=r"(r[3]) : "r"(a));
}
__device__ __forceinline__ void mma16816(float* c, const uint32_t* a, const uint32_t* b){
    asm volatile(
        "mma.sync.aligned.m16n8k16.row.col.f32.f16.f16.f32 "
        "{%0,%1,%2,%3}, {%4,%5,%6,%7}, {%8,%9}, {%0,%1,%2,%3};"
        : "+f"(c[0]), "+f"(c[1]), "+f"(c[2]), "+f"(c[3])
        : "r"(a[0]), "r"(a[1]), "r"(a[2]), "r"(a[3]), "r"(b[0]), "r"(b[1]));
}
#define CPA16(dst, src) \
    asm volatile("cp.async.cg.shared.global [%0], [%1], 16;" :: "r"(dst), "l"(src))
#define CP_COMMIT() asm volatile("cp.async.commit_group;" ::: "memory")
#define CP_WAIT3()  asm volatile("cp.async.wait_group 3;" ::: "memory")

// ---------------------------------------------------------------------------
// GEMM body: NT, fp16 split on tensor cores, 128x256 tile, 512 threads,
// 16 warps with 32x64 warp tiles, BK=32, 5 stages, wait3.
// terms==2: C = Ah*Bh + Al*Bh.  terms==1: C = Ah*Bh (Al unused/not loaded).
// mode 0: C fp32.  mode 1: split fp16 -> (Ch, Cl).  mode 2: fp16 hi only -> Ch.
// ---------------------------------------------------------------------------
__device__ __forceinline__ void gemm_body(
    const __half* __restrict__ Ah, const __half* __restrict__ Al,
    const __half* __restrict__ Bh,
    float* __restrict__ C, __half* __restrict__ Ch, __half* __restrict__ Cl,
    int lda, int ldb, int ldc, float alpha,
    int row0, int col0, int kend, int mode, int terms, char* sm)
{
    const int nch = kend / BK;
    const uint32_t smu = smem_u32(sm);
    const int t = threadIdx.x;

    // ---- producer mapping: 1x16B per thread per 8KB region ----
    const int prow = t >> 2;               // 0..127
    const int pch  = t & 3;                // 16B chunk within 64B row
    const uint32_t dA = SWZ64((uint32_t)(prow * 64 + pch * 16));
    const __half* gAh  = Ah + (long long)(row0 + prow) * lda + pch * 8;
    const __half* gAl  = Al + (long long)(row0 + prow) * lda + pch * 8;
    const __half* gBh0 = Bh + (long long)(col0 + prow) * ldb + pch * 8;
    const __half* gBh1 = Bh + (long long)(col0 + prow + 128) * ldb + pch * 8;

    #define LOAD_CHUNK(s, i) do {                                              \
        uint32_t base = smu + (uint32_t)(s) * STG_BYTES;                       \
        long long kk0 = (long long)(i) * BK;                                   \
        CPA16(base + STG_A_H + dA,        gAh  + kk0);                         \
        if (terms == 2) CPA16(base + STG_A_L + dA, gAl + kk0);                 \
        CPA16(base + STG_B_H + dA,        gBh0 + kk0);                         \
        CPA16(base + STG_B_H + dA + 8192, gBh1 + kk0);                         \
        CP_COMMIT();                                                           \
    } while (0)

    // ---- consumer mapping: 16 warps, warp tile 32x64 (4x4 warp grid) ----
    const int wid  = t >> 5;
    const int lane = t & 31;
    const int m0 = (wid >> 2) * 32;
    const int n0 = (wid & 3) * 64;

    const int rr = lane & 7;
    const int t4 = lane >> 3;
    const int arow = m0 + rr + (t4 & 1) * 8;
    const uint32_t a_base = (uint32_t)(arow * 64 + (t4 >> 1) * 16);
    const uint32_t aswz   = (uint32_t)(((arow >> 1) & 3) << 4);
    const int brw = n0 + rr + (t4 >> 1) * 8;
    const uint32_t b_base = (uint32_t)(brw * 64 + (t4 & 1) * 16);
    const uint32_t bswz   = (uint32_t)(((brw >> 1) & 3) << 4);

    float acc[2][8][4];
    #pragma unroll
    for (int mi = 0; mi < 2; mi++)
        #pragma unroll
        for (int ni = 0; ni < 8; ni++)
            #pragma unroll
            for (int r = 0; r < 4; r++) acc[mi][ni][r] = 0.f;

    int fetch = 0;
    #pragma unroll
    for (int s = 0; s < STAGES - 1; s++) {
        if (fetch < nch) { LOAD_CHUNK(fetch % STAGES, fetch); fetch++; }
        else CP_COMMIT();
    }

    for (int i = 0; i < nch; i++) {
        CP_WAIT3();
        __syncthreads();

        if (fetch < nch) { LOAD_CHUNK(fetch % STAGES, fetch); fetch++; }
        else CP_COMMIT();

        const uint32_t sb = smu + (uint32_t)(i % STAGES) * STG_BYTES;
        #pragma unroll
        for (int ks = 0; ks < 2; ks++) {
            uint32_t ah[2][4], al[2][4];
            #pragma unroll
            for (int mi = 0; mi < 2; mi++) {
                uint32_t o = (a_base + mi * 1024 + ks * 32) ^ aswz;
                ldsm4(ah[mi], sb + STG_A_H + o);
                if (terms == 2) ldsm4(al[mi], sb + STG_A_L + o);
            }
            #pragma unroll
            for (int half = 0; half < 2; half++) {
                uint32_t bh[2][4];
                #pragma unroll
                for (int p = 0; p < 2; p++) {
                    uint32_t o = (b_base + (half * 2 + p) * 1024 + ks * 32) ^ bswz;
                    ldsm4(bh[p], sb + STG_B_H + o);
                }
                #pragma unroll
                for (int mi = 0; mi < 2; mi++)
                    #pragma unroll
                    for (int p = 0; p < 2; p++)
                        #pragma unroll
                        for (int sub = 0; sub < 2; sub++) {
                            int ni = half * 4 + p * 2 + sub;
                            mma16816(acc[mi][ni], ah[mi], bh[p] + 2 * sub);
                            if (terms == 2)
                                mma16816(acc[mi][ni], al[mi], bh[p] + 2 * sub);
                        }
            }
        }
    }

    // -------- epilogue --------
    const int er = lane >> 2;
    const int ec = (lane & 3) * 2;

    if (mode == 0) {
        #pragma unroll
        for (int mi = 0; mi < 2; mi++)
            #pragma unroll
            for (int ni = 0; ni < 8; ni++) {
                int r = row0 + m0 + mi * 16 + er;
                int c = col0 + n0 + ni * 8 + ec;
                float2 v0 = make_float2(acc[mi][ni][0] * alpha, acc[mi][ni][1] * alpha);
                float2 v1 = make_float2(acc[mi][ni][2] * alpha, acc[mi][ni][3] * alpha);
                *(float2*)&C[(long long)r * ldc + c]       = v0;
                *(float2*)&C[(long long)(r + 8) * ldc + c] = v1;
            }
    } else if (mode == 1) {
        #pragma unroll
        for (int mi = 0; mi < 2; mi++)
            #pragma unroll
            for (int ni = 0; ni < 8; ni++) {
                int r = row0 + m0 + mi * 16 + er;
                int c = col0 + n0 + ni * 8 + ec;
                __half h0,h1,h2,h3,l0,l1,l2,l3;
                split1(acc[mi][ni][0] * alpha, h0, l0);
                split1(acc[mi][ni][1] * alpha, h1, l1);
                split1(acc[mi][ni][2] * alpha, h2, l2);
                split1(acc[mi][ni][3] * alpha, h3, l3);
                *(uint32_t*)&Ch[(long long)r * ldc + c]       = pack2(h0, h1);
                *(uint32_t*)&Cl[(long long)r * ldc + c]       = pack2(l0, l1);
                *(uint32_t*)&Ch[(long long)(r + 8) * ldc + c] = pack2(h2, h3);
                *(uint32_t*)&Cl[(long long)(r + 8) * ldc + c] = pack2(l2, l3);
            }
    } else {
        #pragma unroll
        for (int mi = 0; mi < 2; mi++)
            #pragma unroll
            for (int ni = 0; ni < 8; ni++) {
                int r = row0 + m0 + mi * 16 + er;
                int c = col0 + n0 + ni * 8 + ec;
                __half h0 = __float2half_rn(acc[mi][ni][0] * alpha);
                __half h1 = __float2half_rn(acc[mi][ni][1] * alpha);
                __half h2 = __float2half_rn(acc[mi][ni][2] * alpha);
                __half h3 = __float2half_rn(acc[mi][ni][3] * alpha);
                *(uint32_t*)&Ch[(long long)r * ldc + c]       = pack2(h0, h1);
                *(uint32_t*)&Ch[(long long)(r + 8) * ldc + c] = pack2(h2, h3);
            }
    }
    #undef LOAD_CHUNK
}

// ---------------------------------------------------------------------------
// Generic GEMM wrapper (batched via z; causal tile skip; kbound w/ reversed
// row order so longest-K CTAs schedule first).
// ---------------------------------------------------------------------------
__global__ __launch_bounds__(512, 1) void gemm_f16(
    const __half* __restrict__ Ah, const __half* __restrict__ Al,
    const __half* __restrict__ Bh,
    float* __restrict__ C, __half* __restrict__ Ch, __half* __restrict__ Cl,
    int K, int lda, int ldb, int ldc, float alpha,
    long long sA, long long sB, long long sC,
    int causal, int kbound, int mode, int terms)
{
    extern __shared__ char sm[];
    int by = blockIdx.y;
    if (kbound) by = gridDim.y - 1 - by;        // longest-K first
    const int row0 = by * TM;
    const int col0 = blockIdx.x * TN;
    if (causal && col0 > row0 + (TM - 1)) return;

    const long long zo = blockIdx.z;
    const int kend = kbound ? min(K, row0 + TM) : K;

    gemm_body(Ah + zo * sA, Al + zo * sA, Bh + zo * sB,
              C ? C + zo * sC : C,
              Ch ? Ch + zo * sC : Ch,
              Cl ? Cl + zo * sC : Cl,
              lda, ldb, ldc, alpha, row0, col0, kend, mode, terms, sm);
}

// ---------------------------------------------------------------------------
// Merged Gt + Vt launch: grid (8, 8, 5).
//   z in [0,4): Vt[b] = Wv @ x_b^T  (hi only)
//   z == 4    : Gt = 512*scale * Wk^T @ Wq  (hi only; x>=4 idle)
// ---------------------------------------------------------------------------
__global__ __launch_bounds__(512, 1) void gemm_gtvt(
    const __half* __restrict__ wvh, const __half* __restrict__ wvl,
    const __half* __restrict__ xh,
    __half* __restrict__ vth,
    const __half* __restrict__ wkth, const __half* __restrict__ wktl,
    const __half* __restrict__ wqth,
    __half* __restrict__ gth, float galpha)
{
    extern __shared__ char sm[];
    const int row0 = blockIdx.y * TM;
    const int col0 = blockIdx.x * TN;
    if (blockIdx.z < 4) {
        const long long zo = blockIdx.z;
        const long long qkS = (long long)SEQ * CH;
        const long long vtS = (long long)CH * SEQ;
        gemm_body(wvh, wvl, xh + zo * qkS,
                  nullptr, vth + zo * vtS, nullptr,
                  CH, CH, SEQ, 1.f, row0, col0, CH, 2, 2, sm);
    } else {
        if (col0 >= CH) return;   // Gt uses only x < 4
        gemm_body(wkth, wktl, wqth, nullptr, gth, nullptr,
                  CH, CH, CH, galpha, row0, col0, CH, 2, 2, sm);
    }
}

// ---------------------------------------------------------------------------
// Fused preprocessing: split x, split Wv, transpose+split Wq and Wk.
// Flat grid: [0,8192) x-split | [8192,9216) Wv | [9216,10240) WqT | [10240,11264) WkT
// ---------------------------------------------------------------------------
__global__ __launch_bounds__(256) void prep(
    const float* __restrict__ x,  const float* __restrict__ Wq,
    const float* __restrict__ Wk, const float* __restrict__ Wv,
    __half* __restrict__ xh,   __half* __restrict__ xl,
    __half* __restrict__ wvh,  __half* __restrict__ wvl,
    __half* __restrict__ wqth, __half* __restrict__ wqtl,
    __half* __restrict__ wkth, __half* __restrict__ wktl)
{
    const int bid = blockIdx.x;
    const int tid = threadIdx.x;

    if (bid < 9216) {
        const float4* in; uint2 *oh, *ol; int i;
        if (bid < 8192) { in = (const float4*)x;  oh = (uint2*)xh;  ol = (uint2*)xl;  i = bid * 256 + tid; }
        else            { in = (const float4*)Wv; oh = (uint2*)wvh; ol = (uint2*)wvl; i = (bid - 8192) * 256 + tid; }
        float4 v = in[i];
        __half h0,h1,h2,h3,l0,l1,l2,l3;
        split1(v.x,h0,l0); split1(v.y,h1,l1); split1(v.z,h2,l2); split1(v.w,h3,l3);
        uint2 H, L;
        H.x = pack2(h0,h1); H.y = pack2(h2,h3);
        L.x = pack2(l0,l1); L.y = pack2(l2,l3);
        oh[i] = H; ol[i] = L;
        return;
    }

    __shared__ float tile[32][33];
    const float* in; __half *oh, *ol; int id;
    if (bid < 10240) { in = Wq; oh = wqth; ol = wqtl; id = bid - 9216; }
    else             { in = Wk; oh = wkth; ol = wktl; id = bid - 10240; }
    const int bx = (id & 31) * 32, by = (id >> 5) * 32;
    const int tx = tid & 31, ty = tid >> 5;
    #pragma unroll
    for (int i = 0; i < 4; i++) {
        int r = ty + i * 8;
        tile[r][tx] = in[(long long)(by + r) * CH + bx + tx];
    }
    __syncthreads();
    #pragma unroll
    for (int i = 0; i < 4; i++) {
        int r = ty + i * 8;
        float v = tile[tx][r];
        __half h, l; split1(v, h, l);
        long long o = (long long)(bx + r) * CH + by + tx;
        oh[o] = h; ol[o] = l;
    }
}

// ---------------------------------------------------------------------------
// Causal row softmax: S fp32 -> fp16 P (hi only). Zero fill to kmax.
// ---------------------------------------------------------------------------
__global__ __launch_bounds__(256) void softmax_p(
    const float* __restrict__ S, __half* __restrict__ Ph, int T)
{
    const int q = blockIdx.x;
    const long long off = ((long long)blockIdx.y * T + q) * (long long)T;
    const float* row = S + off;

    __shared__ float buf[SEQ];
    __shared__ float red[8];

    const int t = threadIdx.x;
    const int n = q + 1;
    const int kmax = (q & ~(TM - 1)) + TM;

    float lmax = -3.0e38f;
    for (int i = t; i < n; i += 256) {
        float v = row[i];
        buf[i] = v;
        lmax = fmaxf(lmax, v);
    }
    #pragma unroll
    for (int o = 16; o; o >>= 1) lmax = fmaxf(lmax, __shfl_xor_sync(0xFFFFFFFFu, lmax, o));
    if ((t & 31) == 0) red[t >> 5] = lmax;
    __syncthreads();
    if (t < 32) {
        float v = (t < 8) ? red[t] : -3.0e38f;
        #pragma unroll
        for (int o = 4; o; o >>= 1) v = fmaxf(v, __shfl_xor_sync(0xFFFFFFFFu, v, o));
        if (t == 0) red[0] = v;
    }
    __syncthreads();
    const float gmax = red[0];

    float lsum = 0.f;
    for (int i = t; i < n; i += 256) {
        float e = __expf(buf[i] - gmax);
        buf[i] = e;
        lsum += e;
    }
    __syncthreads();
    #pragma unroll
    for (int o = 16; o; o >>= 1) lsum += __shfl_xor_sync(0xFFFFFFFFu, lsum, o);
    if ((t & 31) == 0) red[t >> 5] = lsum;
    __syncthreads();
    if (t < 32) {
        float v = (t < 8) ? red[t] : 0.f;
        #pragma unroll
        for (int o = 4; o; o >>= 1) v += __shfl_xor_sync(0xFFFFFFFFu, v, o);
        if (t == 0) red[0] = v;
    }
    __syncthreads();
    const float inv = 1.f / red[0];

    for (int i = t; i < kmax; i += 256) {
        float v = (i < n) ? buf[i] * inv : 0.f;
        Ph[off + i] = __float2half_rn(v);
    }
}

// ---------------------------------------------------------------------------
extern "C" void kernel_launch(void* const* d_in, const int* in_sizes, int n_in,
                              void* d_out, int out_size)
{
    (void)in_sizes; (void)n_in; (void)out_size;
    const float* x  = (const float*)d_in[0];
    const float* Wq = (const float*)d_in[1];
    const float* Wk = (const float*)d_in[2];
    const float* Wv = (const float*)d_in[3];
    float* out = (float*)d_out;

    __half *xh,*xl,*wqth,*wqtl,*wkth,*wktl,*wvh,*wvl,*gth;
    __half *yh,*yl,*vth,*ph;
    float* s;
    cudaGetSymbolAddress((void**)&xh,   g_xh);   cudaGetSymbolAddress((void**)&xl,   g_xl);
    cudaGetSymbolAddress((void**)&wqth, g_wqth); cudaGetSymbolAddress((void**)&wqtl, g_wqtl);
    cudaGetSymbolAddress((void**)&wkth, g_wkth); cudaGetSymbolAddress((void**)&wktl, g_wktl);
    cudaGetSymbolAddress((void**)&wvh,  g_wvh);  cudaGetSymbolAddress((void**)&wvl,  g_wvl);
    cudaGetSymbolAddress((void**)&gth,  g_gth);
    cudaGetSymbolAddress((void**)&yh,   g_yh);   cudaGetSymbolAddress((void**)&yl,   g_yl);
    cudaGetSymbolAddress((void**)&vth,  g_vth);
    cudaGetSymbolAddress((void**)&ph,   g_ph);
    cudaGetSymbolAddress((void**)&s,    g_S);

    cudaFuncSetAttribute(gemm_f16,  cudaFuncAttributeMaxDynamicSharedMemorySize, SMEM_BYTES);
    cudaFuncSetAttribute(gemm_gtvt, cudaFuncAttributeMaxDynamicSharedMemorySize, SMEM_BYTES);

    const int M = BATCH * SEQ;                          // 8192
    const long long qkS = (long long)SEQ * CH;
    const long long vtS = (long long)CH * SEQ;
    const long long sS  = (long long)SEQ * SEQ;

    dim3 blk(512);

    // 0) fused preprocessing (x split, Wv split, WqT, WkT)
    prep<<<11264, 256>>>(x, Wq, Wk, Wv, xh, xl, wvh, wvl, wqth, wqtl, wkth, wktl);

    // 1) merged: Vt[b] = Wv @ x_b^T  and  Gt = 512*scale * Wk^T @ Wq
    //    scale = 1/32 -> galpha = 512/32 = 16
    gemm_gtvt<<<dim3(8, 8, 5), blk, SMEM_BYTES>>>(wvh, wvl, xh, vth,
                                                  wkth, wktl, wqth, gth, 16.f);

    // 2) Y*16 = x @ Gt^T / 32 (NT), split out   [8192, 1024]
    dim3 gy(CH / TN, M / TM, 1);
    gemm_f16<<<gy, blk, SMEM_BYTES>>>(xh, xl, gth, nullptr, yh, yl,
                                      CH, CH, CH, CH, 1.f / 32.f, 0, 0, 0, 0, 0, 1, 2);

    // 3) S = (Y*16) @ x^T / 16 per batch (NT, causal tile skip) -> fp32
    dim3 g2(SEQ / TN, SEQ / TM, BATCH);
    gemm_f16<<<g2, blk, SMEM_BYTES>>>(yh, yl, xh, s, nullptr, nullptr,
                                      CH, CH, CH, SEQ, 1.f / 16.f, qkS, qkS, sS, 1, 0, 0, 2);

    // 4) softmax -> P hi only
    softmax_p<<<dim3(SEQ, BATCH), 256>>>(s, ph, SEQ);

    // 5) out = Ph @ (V^T)^T per batch (single-term NT, causal k-bound, rows reversed)
    dim3 g3(CH / TN, SEQ / TM, BATCH);
    gemm_f16<<<g3, blk, SMEM_BYTES>>>(ph, ph, vth, out, nullptr, nullptr,
                                      SEQ, SEQ, SEQ, CH, 1.f, sS, vtS, qkS, 0, 1, 0, 1);
}

// round 16
// speedup vs baseline: 1.1280x; 1.1280x over previous
#include <cuda_runtime.h>
#include <cuda_fp16.h>
#include <cstdint>

// Shape fixed by dataset: B=4, T=2048, C=1024, fp32 in/out.
#define BATCH 4
#define SEQ   2048
#define CH    1024

#define TM 128
#define TN 256
#define BK 32          // K elems per chunk (fp16) = 64B rows
#define STAGES 5

#define SWZ64(o) ((o) ^ ((((unsigned)(o)) >> 3) & 0x30u))

// ---------------- scratch (__device__ globals; no allocs allowed) -------------
__device__ __half g_xh[(size_t)BATCH*SEQ*CH], g_xl[(size_t)BATCH*SEQ*CH];
__device__ __half g_wqth[CH*CH], g_wqtl[CH*CH];   // Wq^T split
__device__ __half g_wkth[CH*CH], g_wktl[CH*CH];   // Wk^T split
__device__ __half g_wvh[CH*CH],  g_wvl[CH*CH];
__device__ __half g_gth[CH*CH];                   // Gt = 512*scale*(Wk^T Wq), hi only
__device__ __half g_yh[(size_t)BATCH*SEQ*CH], g_yl[(size_t)BATCH*SEQ*CH];   // Y*16 split
__device__ __half g_vth[(size_t)BATCH*CH*SEQ];    // V^T [b][c][t], hi only
__device__ float  g_S [(size_t)BATCH*SEQ*SEQ];
__device__ __half g_ph[(size_t)BATCH*SEQ*SEQ];    // P hi only

// ---------------- helpers ----------------
__device__ __forceinline__ uint32_t smem_u32(const void* p){
    uint32_t a;
    asm("{ .reg .u64 t; cvta.to.shared.u64 t, %1; cvt.u32.u64 %0, t; }" : "=r"(a) : "l"(p));
    return a;
}
__device__ __forceinline__ void split1(float v, __half& h, __half& l){
    h = __float2half_rn(v);
    l = __float2half_rn(v - __half2float(h));
}
__device__ __forceinline__ uint32_t pack2(__half a, __half b){
    __half2 p = __halves2half2(a, b);
    return *(uint32_t*)&p;
}
__device__ __forceinline__ void ldsm4(uint32_t* r, uint32_t a){
    asm volatile("ldmatrix.sync.aligned.m8n8.x4.shared.b16 {%0,%1,%2,%3}, [%4];"
        : "=r"(r[0]),"=r"(r[1]),"=r"(r[2]),"=r"(r[3]) : "r"(a));
}
__device__ __forceinline__ void mma16816(float* c, const uint32_t* a, const uint32_t* b){
    asm volatile(
        "mma.sync.aligned.m16n8k16.row.col.f32.f16.f16.f32 "
        "{%0,%1,%2,%3}, {%4,%5,%6,%7}, {%8,%9}, {%0,%1,%2,%3};"
        : "+f"(c[0]), "+f"(c[1]), "+f"(c[2]), "+f"(c[3])
        : "r"(a[0]), "r"(a[1]), "r"(a[2]), "r"(a[3]), "r"(b[0]), "r"(b[1]));
}
#define CPA16(dst, src) \
    asm volatile("cp.async.cg.shared.global [%0], [%1], 16;" :: "r"(dst), "l"(src))
#define CP_COMMIT() asm volatile("cp.async.commit_group;" ::: "memory")
#define CP_WAIT3()  asm volatile("cp.async.wait_group 3;" ::: "memory")

// ---------------------------------------------------------------------------
// GEMM body (compile-time TERMS): NT, fp16 split, 128x256 tile, 512 threads,
// 16 warps with 32x64 warp tiles, BK=32, 5 stages, wait3.
// TERMS==2: C = Ah*Bh + Al*Bh (smem stage 32KB: A_H|A_L|B_H).
// TERMS==1: C = Ah*Bh          (smem stage 24KB: A_H|B_H, no lo plane).
// mode 0: C fp32.  mode 1: split fp16 -> (Ch, Cl).  mode 2: fp16 hi only -> Ch.
// ---------------------------------------------------------------------------
template<int TERMS>
__device__ __forceinline__ void gemm_body(
    const __half* __restrict__ Ah, const __half* __restrict__ Al,
    const __half* __restrict__ Bh,
    float* __restrict__ C, __half* __restrict__ Ch, __half* __restrict__ Cl,
    int lda, int ldb, int ldc, float alpha,
    int row0, int col0, int kend, int mode, char* sm)
{
    constexpr uint32_t OFF_A_H = 0;
    constexpr uint32_t OFF_A_L = 8192;                          // TERMS==2 only
    constexpr uint32_t OFF_B_H = (TERMS == 2) ? 16384 : 8192;
    constexpr uint32_t STG     = (TERMS == 2) ? 32768 : 24576;

    const int nch = kend / BK;
    const uint32_t smu = smem_u32(sm);
    const int t = threadIdx.x;

    // ---- producer mapping: 1x16B per thread per 8KB region ----
    const int prow = t >> 2;               // 0..127
    const int pch  = t & 3;                // 16B chunk within 64B row
    const uint32_t dA = SWZ64((uint32_t)(prow * 64 + pch * 16));
    const __half* gAh  = Ah + (long long)(row0 + prow) * lda + pch * 8;
    const __half* gAl  = Al + (long long)(row0 + prow) * lda + pch * 8;
    const __half* gBh0 = Bh + (long long)(col0 + prow) * ldb + pch * 8;
    const __half* gBh1 = Bh + (long long)(col0 + prow + 128) * ldb + pch * 8;

    #define LOAD_CHUNK(s, i) do {                                              \
        uint32_t base = smu + (uint32_t)(s) * STG;                             \
        long long kk0 = (long long)(i) * BK;                                   \
        CPA16(base + OFF_A_H + dA,        gAh  + kk0);                         \
        if (TERMS == 2) CPA16(base + OFF_A_L + dA, gAl + kk0);                 \
        CPA16(base + OFF_B_H + dA,        gBh0 + kk0);                         \
        CPA16(base + OFF_B_H + dA + 8192, gBh1 + kk0);                         \
        CP_COMMIT();                                                           \
    } while (0)

    // ---- consumer mapping: 16 warps, warp tile 32x64 (4x4 warp grid) ----
    const int wid  = t >> 5;
    const int lane = t & 31;
    const int m0 = (wid >> 2) * 32;
    const int n0 = (wid & 3) * 64;

    const int rr = lane & 7;
    const int t4 = lane >> 3;
    const int arow = m0 + rr + (t4 & 1) * 8;
    const uint32_t a_base = (uint32_t)(arow * 64 + (t4 >> 1) * 16);
    const uint32_t aswz   = (uint32_t)(((arow >> 1) & 3) << 4);
    const int brw = n0 + rr + (t4 >> 1) * 8;
    const uint32_t b_base = (uint32_t)(brw * 64 + (t4 & 1) * 16);
    const uint32_t bswz   = (uint32_t)(((brw >> 1) & 3) << 4);

    float acc[2][8][4];
    #pragma unroll
    for (int mi = 0; mi < 2; mi++)
        #pragma unroll
        for (int ni = 0; ni < 8; ni++)
            #pragma unroll
            for (int r = 0; r < 4; r++) acc[mi][ni][r] = 0.f;

    int fetch = 0;
    #pragma unroll
    for (int s = 0; s < STAGES - 1; s++) {
        if (fetch < nch) { LOAD_CHUNK(fetch % STAGES, fetch); fetch++; }
        else CP_COMMIT();
    }

    for (int i = 0; i < nch; i++) {
        CP_WAIT3();
        __syncthreads();

        if (fetch < nch) { LOAD_CHUNK(fetch % STAGES, fetch); fetch++; }
        else CP_COMMIT();

        const uint32_t sb = smu + (uint32_t)(i % STAGES) * STG;
        #pragma unroll
        for (int ks = 0; ks < 2; ks++) {
            uint32_t ah[2][4], al[2][4];
            #pragma unroll
            for (int mi = 0; mi < 2; mi++) {
                uint32_t o = (a_base + mi * 1024 + ks * 32) ^ aswz;
                ldsm4(ah[mi], sb + OFF_A_H + o);
                if (TERMS == 2) ldsm4(al[mi], sb + OFF_A_L + o);
            }
            #pragma unroll
            for (int half = 0; half < 2; half++) {
                uint32_t bh[2][4];
                #pragma unroll
                for (int p = 0; p < 2; p++) {
                    uint32_t o = (b_base + (half * 2 + p) * 1024 + ks * 32) ^ bswz;
                    ldsm4(bh[p], sb + OFF_B_H + o);
                }
                #pragma unroll
                for (int mi = 0; mi < 2; mi++)
                    #pragma unroll
                    for (int p = 0; p < 2; p++)
                        #pragma unroll
                        for (int sub = 0; sub < 2; sub++) {
                            int ni = half * 4 + p * 2 + sub;
                            mma16816(acc[mi][ni], ah[mi], bh[p] + 2 * sub);
                            if (TERMS == 2)
                                mma16816(acc[mi][ni], al[mi], bh[p] + 2 * sub);
                        }
            }
        }
    }

    // -------- epilogue --------
    const int er = lane >> 2;
    const int ec = (lane & 3) * 2;

    if (mode == 0) {
        #pragma unroll
        for (int mi = 0; mi < 2; mi++)
            #pragma unroll
            for (int ni = 0; ni < 8; ni++) {
                int r = row0 + m0 + mi * 16 + er;
                int c = col0 + n0 + ni * 8 + ec;
                float2 v0 = make_float2(acc[mi][ni][0] * alpha, acc[mi][ni][1] * alpha);
                float2 v1 = make_float2(acc[mi][ni][2] * alpha, acc[mi][ni][3] * alpha);
                *(float2*)&C[(long long)r * ldc + c]       = v0;
                *(float2*)&C[(long long)(r + 8) * ldc + c] = v1;
            }
    } else if (mode == 1) {
        #pragma unroll
        for (int mi = 0; mi < 2; mi++)
            #pragma unroll
            for (int ni = 0; ni < 8; ni++) {
                int r = row0 + m0 + mi * 16 + er;
                int c = col0 + n0 + ni * 8 + ec;
                __half h0,h1,h2,h3,l0,l1,l2,l3;
                split1(acc[mi][ni][0] * alpha, h0, l0);
                split1(acc[mi][ni][1] * alpha, h1, l1);
                split1(acc[mi][ni][2] * alpha, h2, l2);
                split1(acc[mi][ni][3] * alpha, h3, l3);
                *(uint32_t*)&Ch[(long long)r * ldc + c]       = pack2(h0, h1);
                *(uint32_t*)&Cl[(long long)r * ldc + c]       = pack2(l0, l1);
                *(uint32_t*)&Ch[(long long)(r + 8) * ldc + c] = pack2(h2, h3);
                *(uint32_t*)&Cl[(long long)(r + 8) * ldc + c] = pack2(l2, l3);
            }
    } else {
        #pragma unroll
        for (int mi = 0; mi < 2; mi++)
            #pragma unroll
            for (int ni = 0; ni < 8; ni++) {
                int r = row0 + m0 + mi * 16 + er;
                int c = col0 + n0 + ni * 8 + ec;
                __half h0 = __float2half_rn(acc[mi][ni][0] * alpha);
                __half h1 = __float2half_rn(acc[mi][ni][1] * alpha);
                __half h2 = __float2half_rn(acc[mi][ni][2] * alpha);
                __half h3 = __float2half_rn(acc[mi][ni][3] * alpha);
                *(uint32_t*)&Ch[(long long)r * ldc + c]       = pack2(h0, h1);
                *(uint32_t*)&Ch[(long long)(r + 8) * ldc + c] = pack2(h2, h3);
            }
    }
    #undef LOAD_CHUNK
}

// ---------------------------------------------------------------------------
// Generic GEMM wrapper (batched via z; causal tile skip; kbound w/ reversed
// row order so longest-K CTAs schedule first).
// ---------------------------------------------------------------------------
template<int TERMS>
__global__ __launch_bounds__(512, 1) void gemm_f16(
    const __half* __restrict__ Ah, const __half* __restrict__ Al,
    const __half* __restrict__ Bh,
    float* __restrict__ C, __half* __restrict__ Ch, __half* __restrict__ Cl,
    int K, int lda, int ldb, int ldc, float alpha,
    long long sA, long long sB, long long sC,
    int causal, int kbound, int mode)
{
    extern __shared__ char sm[];
    int by = blockIdx.y;
    if (kbound) by = gridDim.y - 1 - by;        // longest-K first
    const int row0 = by * TM;
    const int col0 = blockIdx.x * TN;
    if (causal && col0 > row0 + (TM - 1)) return;

    const long long zo = blockIdx.z;
    const int kend = kbound ? min(K, row0 + TM) : K;

    gemm_body<TERMS>(Ah + zo * sA, Al + zo * sA, Bh + zo * sB,
                     C ? C + zo * sC : C,
                     Ch ? Ch + zo * sC : Ch,
                     Cl ? Cl + zo * sC : Cl,
                     lda, ldb, ldc, alpha, row0, col0, kend, mode, sm);
}

// ---------------------------------------------------------------------------
// Merged Gt + Vt launch: grid (8, 8, 5).
//   z in [0,4): Vt[b] = Wv @ x_b^T  (hi only)
//   z == 4    : Gt = 512*scale * Wk^T @ Wq  (hi only; x>=4 idle)
// ---------------------------------------------------------------------------
__global__ __launch_bounds__(512, 1) void gemm_gtvt(
    const __half* __restrict__ wvh, const __half* __restrict__ wvl,
    const __half* __restrict__ xh,
    __half* __restrict__ vth,
    const __half* __restrict__ wkth, const __half* __restrict__ wktl,
    const __half* __restrict__ wqth,
    __half* __restrict__ gth, float galpha)
{
    extern __shared__ char sm[];
    const int row0 = blockIdx.y * TM;
    const int col0 = blockIdx.x * TN;
    if (blockIdx.z < 4) {
        const long long zo = blockIdx.z;
        const long long qkS = (long long)SEQ * CH;
        const long long vtS = (long long)CH * SEQ;
        gemm_body<2>(wvh, wvl, xh + zo * qkS,
                     nullptr, vth + zo * vtS, nullptr,
                     CH, CH, SEQ, 1.f, row0, col0, CH, 2, sm);
    } else {
        if (col0 >= CH) return;   // Gt uses only x < 4
        gemm_body<2>(wkth, wktl, wqth, nullptr, gth, nullptr,
                     CH, CH, CH, galpha, row0, col0, CH, 2, sm);
    }
}

// ---------------------------------------------------------------------------
// Fused preprocessing: split x, split Wv, transpose+split Wq and Wk.
// Flat grid: [0,8192) x-split | [8192,9216) Wv | [9216,10240) WqT | [10240,11264) WkT
// ---------------------------------------------------------------------------
__global__ __launch_bounds__(256) void prep(
    const float* __restrict__ x,  const float* __restrict__ Wq,
    const float* __restrict__ Wk, const float* __restrict__ Wv,
    __half* __restrict__ xh,   __half* __restrict__ xl,
    __half* __restrict__ wvh,  __half* __restrict__ wvl,
    __half* __restrict__ wqth, __half* __restrict__ wqtl,
    __half* __restrict__ wkth, __half* __restrict__ wktl)
{
    const int bid = blockIdx.x;
    const int tid = threadIdx.x;

    if (bid < 9216) {
        const float4* in; uint2 *oh, *ol; int i;
        if (bid < 8192) { in = (const float4*)x;  oh = (uint2*)xh;  ol = (uint2*)xl;  i = bid * 256 + tid; }
        else            { in = (const float4*)Wv; oh = (uint2*)wvh; ol = (uint2*)wvl; i = (bid - 8192) * 256 + tid; }
        float4 v = in[i];
        __half h0,h1,h2,h3,l0,l1,l2,l3;
        split1(v.x,h0,l0); split1(v.y,h1,l1); split1(v.z,h2,l2); split1(v.w,h3,l3);
        uint2 H, L;
        H.x = pack2(h0,h1); H.y = pack2(h2,h3);
        L.x = pack2(l0,l1); L.y = pack2(l2,l3);
        oh[i] = H; ol[i] = L;
        return;
    }

    __shared__ float tile[32][33];
    const float* in; __half *oh, *ol; int id;
    if (bid < 10240) { in = Wq; oh = wqth; ol = wqtl; id = bid - 9216; }
    else             { in = Wk; oh = wkth; ol = wktl; id = bid - 10240; }
    const int bx = (id & 31) * 32, by = (id >> 5) * 32;
    const int tx = tid & 31, ty = tid >> 5;
    #pragma unroll
    for (int i = 0; i < 4; i++) {
        int r = ty + i * 8;
        tile[r][tx] = in[(long long)(by + r) * CH + bx + tx];
    }
    __syncthreads();
    #pragma unroll
    for (int i = 0; i < 4; i++) {
        int r = ty + i * 8;
        float v = tile[tx][r];
        __half h, l; split1(v, h, l);
        long long o = (long long)(bx + r) * CH + by + tx;
        oh[o] = h; ol[o] = l;
    }
}

// ---------------------------------------------------------------------------
// Causal row softmax: S fp32 -> fp16 P (hi only). Zero fill to kmax.
// ---------------------------------------------------------------------------
__global__ __launch_bounds__(256) void softmax_p(
    const float* __restrict__ S, __half* __restrict__ Ph, int T)
{
    const int q = blockIdx.x;
    const long long off = ((long long)blockIdx.y * T + q) * (long long)T;
    const float* row = S + off;

    __shared__ float buf[SEQ];
    __shared__ float red[8];

    const int t = threadIdx.x;
    const int n = q + 1;
    const int kmax = (q & ~(TM - 1)) + TM;

    float lmax = -3.0e38f;
    for (int i = t; i < n; i += 256) {
        float v = row[i];
        buf[i] = v;
        lmax = fmaxf(lmax, v);
    }
    #pragma unroll
    for (int o = 16; o; o >>= 1) lmax = fmaxf(lmax, __shfl_xor_sync(0xFFFFFFFFu, lmax, o));
    if ((t & 31) == 0) red[t >> 5] = lmax;
    __syncthreads();
    if (t < 32) {
        float v = (t < 8) ? red[t] : -3.0e38f;
        #pragma unroll
        for (int o = 4; o; o >>= 1) v = fmaxf(v, __shfl_xor_sync(0xFFFFFFFFu, v, o));
        if (t == 0) red[0] = v;
    }
    __syncthreads();
    const float gmax = red[0];

    float lsum = 0.f;
    for (int i = t; i < n; i += 256) {
        float e = __expf(buf[i] - gmax);
        buf[i] = e;
        lsum += e;
    }
    __syncthreads();
    #pragma unroll
    for (int o = 16; o; o >>= 1) lsum += __shfl_xor_sync(0xFFFFFFFFu, lsum, o);
    if ((t & 31) == 0) red[t >> 5] = lsum;
    __syncthreads();
    if (t < 32) {
        float v = (t < 8) ? red[t] : 0.f;
        #pragma unroll
        for (int o = 4; o; o >>= 1) v += __shfl_xor_sync(0xFFFFFFFFu, v, o);
        if (t == 0) red[0] = v;
    }
    __syncthreads();
    const float inv = 1.f / red[0];

    for (int i = t; i < kmax; i += 256) {
        float v = (i < n) ? buf[i] * inv : 0.f;
        Ph[off + i] = __float2half_rn(v);
    }
}

// ---------------------------------------------------------------------------
extern "C" void kernel_launch(void* const* d_in, const int* in_sizes, int n_in,
                              void* d_out, int out_size)
{
    (void)in_sizes; (void)n_in; (void)out_size;
    const float* x  = (const float*)d_in[0];
    const float* Wq = (const float*)d_in[1];
    const float* Wk = (const float*)d_in[2];
    const float* Wv = (const float*)d_in[3];
    float* out = (float*)d_out;

    __half *xh,*xl,*wqth,*wqtl,*wkth,*wktl,*wvh,*wvl,*gth;
    __half *yh,*yl,*vth,*ph;
    float* s;
    cudaGetSymbolAddress((void**)&xh,   g_xh);   cudaGetSymbolAddress((void**)&xl,   g_xl);
    cudaGetSymbolAddress((void**)&wqth, g_wqth); cudaGetSymbolAddress((void**)&wqtl, g_wqtl);
    cudaGetSymbolAddress((void**)&wkth, g_wkth); cudaGetSymbolAddress((void**)&wktl, g_wktl);
    cudaGetSymbolAddress((void**)&wvh,  g_wvh);  cudaGetSymbolAddress((void**)&wvl,  g_wvl);
    cudaGetSymbolAddress((void**)&gth,  g_gth);
    cudaGetSymbolAddress((void**)&yh,   g_yh);   cudaGetSymbolAddress((void**)&yl,   g_yl);
    cudaGetSymbolAddress((void**)&vth,  g_vth);
    cudaGetSymbolAddress((void**)&ph,   g_ph);
    cudaGetSymbolAddress((void**)&s,    g_S);

    const int SMEM2 = STAGES * 32768;   // 160 KB (2-term)
    const int SMEM1 = STAGES * 24576;   // 120 KB (1-term)
    cudaFuncSetAttribute(gemm_f16<2>, cudaFuncAttributeMaxDynamicSharedMemorySize, SMEM2);
    cudaFuncSetAttribute(gemm_f16<1>, cudaFuncAttributeMaxDynamicSharedMemorySize, SMEM1);
    cudaFuncSetAttribute(gemm_gtvt,   cudaFuncAttributeMaxDynamicSharedMemorySize, SMEM2);

    const int M = BATCH * SEQ;                          // 8192
    const long long qkS = (long long)SEQ * CH;
    const long long vtS = (long long)CH * SEQ;
    const long long sS  = (long long)SEQ * SEQ;

    dim3 blk(512);

    // 0) fused preprocessing (x split, Wv split, WqT, WkT)
    prep<<<11264, 256>>>(x, Wq, Wk, Wv, xh, xl, wvh, wvl, wqth, wqtl, wkth, wktl);

    // 1) merged: Vt[b] = Wv @ x_b^T  and  Gt = 512*scale * Wk^T @ Wq
    //    scale = 1/32 -> galpha = 512/32 = 16
    gemm_gtvt<<<dim3(8, 8, 5), blk, SMEM2>>>(wvh, wvl, xh, vth,
                                             wkth, wktl, wqth, gth, 16.f);

    // 2) Y*16 = x @ Gt^T / 32 (NT), split out   [8192, 1024]
    dim3 gy(CH / TN, M / TM, 1);
    gemm_f16<2><<<gy, blk, SMEM2>>>(xh, xl, gth, nullptr, yh, yl,
                                    CH, CH, CH, CH, 1.f / 32.f, 0, 0, 0, 0, 0, 1);

    // 3) S = (Y*16) @ x^T / 16 per batch (NT, causal tile skip) -> fp32
    dim3 g2(SEQ / TN, SEQ / TM, BATCH);
    gemm_f16<2><<<g2, blk, SMEM2>>>(yh, yl, xh, s, nullptr, nullptr,
                                    CH, CH, CH, SEQ, 1.f / 16.f, qkS, qkS, sS, 1, 0, 0);

    // 4) softmax -> P hi only
    softmax_p<<<dim3(SEQ, BATCH), 256>>>(s, ph, SEQ);

    // 5) out = Ph @ (V^T)^T per batch (single-term NT, causal k-bound, rows reversed)
    dim3 g3(CH / TN, SEQ / TM, BATCH);
    gemm_f16<1><<<g3, blk, SMEM1>>>(ph, ph, vth, out, nullptr, nullptr,
                                    SEQ, SEQ, SEQ, CH, 1.f, sS, vtS, qkS, 0, 1, 0);
}